// round 1
// baseline (speedup 1.0000x reference)
#include <cuda_runtime.h>
#include <math.h>

// ProbSparseAttention: B=2,H=8,L=4096,D=64, num_keys=num_queries=45
#define BB 2
#define HH 8
#define LL 4096
#define DD 64
#define BH (BB*HH)
#define NK 45
#define NQ 45
#define NSPLIT 16
#define CK 256            // keys per attention chunk
#define KP 260            // Kt (transposed K) row stride in floats
#define VP 68             // Vs row stride in floats
#define NEGINF (-1e30f)

// ---------------- scratch (device globals; no allocation allowed) ----------------
__device__ float g_sparsity[BH * LL];
__device__ int   g_qidx[BH * NQ];
__device__ float g_pm[BH * NQ * NSPLIT];
__device__ float g_pl[BH * NQ * NSPLIT];
__device__ float g_pacc[BH * NQ * NSPLIT * DD];
__device__ float g_csum[BH * 64 * DD];
__device__ float g_coff[BH * 64 * DD];

// ---------------- Stage A: sparsity = max(scores_45) - sum(scores_45)/L ----------------
// One warp per query. Lane j handles sampled keys j and j+32 (j<13).
__global__ void k_sparsity(const float* __restrict__ q,
                           const float* __restrict__ key,
                           const int* __restrict__ kidx) {
    __shared__ float qs[8 * DD];
    int w = threadIdx.x >> 5, lane = threadIdx.x & 31;
    int bh = blockIdx.x >> 9;                   // 512 blocks per bh (4096/8)
    int qrow = ((blockIdx.x & 511) << 3) + w;

    // stage q row into smem (warp-local)
    float2 qv = ((const float2*)q)[((long)bh * LL + qrow) * 32 + lane];
    ((float2*)qs)[w * 32 + lane] = qv;
    __syncwarp();

    const float4* qs4 = (const float4*)(qs + w * DD);
    const float4* k4 = (const float4*)key;

    int i0 = kidx[qrow * NK + lane];
    bool has1 = (lane < NK - 32);               // lane < 13
    int i1 = has1 ? kidx[qrow * NK + lane + 32] : 0;
    const float4* kr0 = k4 + ((long)bh * LL + i0) * 16;
    const float4* kr1 = k4 + ((long)bh * LL + i1) * 16;

    float s0 = 0.f, s1 = 0.f;
#pragma unroll
    for (int t = 0; t < 16; t++) {
        float4 qq = qs4[t];
        float4 a = kr0[t];
        s0 += qq.x * a.x + qq.y * a.y + qq.z * a.z + qq.w * a.w;
        float4 b = kr1[t];
        s1 += qq.x * b.x + qq.y * b.y + qq.z * b.z + qq.w * b.w;
    }
    float mymax = has1 ? fmaxf(s0, s1) : s0;
    float mysum = s0 + (has1 ? s1 : 0.f);
#pragma unroll
    for (int o = 16; o > 0; o >>= 1) {
        mymax = fmaxf(mymax, __shfl_xor_sync(0xffffffffu, mymax, o));
        mysum += __shfl_xor_sync(0xffffffffu, mysum, o);
    }
    if (lane == 0)
        g_sparsity[bh * LL + qrow] = mymax - mysum * (1.0f / LL);
}

// ---------------- Stage B: top-45 per (b,h) ----------------
// jax.lax.top_k tie-break: smaller index wins on equal value.
__global__ void k_topk() {
    __shared__ float vals[LL];
    __shared__ float rv[256];
    __shared__ int ri[256];
    int bh = blockIdx.x, tid = threadIdx.x;
    for (int i = tid; i < LL; i += 256) vals[i] = g_sparsity[bh * LL + i];
    __syncthreads();
    for (int it = 0; it < NQ; it++) {
        float bv = -1e38f; int bi = 0;
        for (int i = tid; i < LL; i += 256) {
            float v = vals[i];
            if (v > bv || (v == bv && i < bi)) { bv = v; bi = i; }
        }
        rv[tid] = bv; ri[tid] = bi;
        __syncthreads();
        for (int s = 128; s > 0; s >>= 1) {
            if (tid < s) {
                float ov = rv[tid + s]; int oi = ri[tid + s];
                if (ov > rv[tid] || (ov == rv[tid] && oi < ri[tid])) { rv[tid] = ov; ri[tid] = oi; }
            }
            __syncthreads();
        }
        if (tid == 0) { g_qidx[bh * NQ + it] = ri[0]; vals[ri[0]] = -1e38f; }
        __syncthreads();
    }
}

// ---------------- Stage C: split-K attention over chunks of 256 keys ----------------
// Block = (split, bh). K chunk staged transposed (Kt[d][k]), V row-major.
// Warp w handles query slots w, w+8, ... Online softmax partials per (slot, split).
__global__ void __launch_bounds__(256, 1)
k_attn(const float* __restrict__ q,
       const float* __restrict__ key,
       const float* __restrict__ val) {
    extern __shared__ float sm[];
    float* Kt = sm;                       // DD*KP
    float* Vs = Kt + DD * KP;             // CK*VP
    float* qs = Vs + CK * VP;             // NQ*DD
    float* ps = qs + NQ * DD;             // 8*CK
    int* qis = (int*)(ps + 8 * CK);       // NQ

    int split = blockIdx.x, bh = blockIdx.y;
    int tid = threadIdx.x, w = tid >> 5, lane = tid & 31;
    int cs = split * CK;

    if (tid < NQ) qis[tid] = g_qidx[bh * NQ + tid];
    __syncthreads();

    // stage selected query rows
    for (int i = tid; i < NQ * DD / 4; i += 256) {
        int slot = i >> 4, d4 = i & 15;
        float4 v = ((const float4*)q)[((long)bh * LL + qis[slot]) * 16 + d4];
        ((float4*)qs)[i] = v;
    }
    // stage K (transposed) and V chunk
    const float4* k4 = (const float4*)key + ((long)bh * LL + cs) * 16;
    const float4* v4 = (const float4*)val + ((long)bh * LL + cs) * 16;
#pragma unroll
    for (int it = 0; it < 16; it++) {
        int idx = tid + it * 256;         // 0..4095 float4s
        int kk = idx >> 4, d4 = idx & 15;
        float4 a = k4[idx];
        Kt[(4 * d4 + 0) * KP + kk] = a.x;
        Kt[(4 * d4 + 1) * KP + kk] = a.y;
        Kt[(4 * d4 + 2) * KP + kk] = a.z;
        Kt[(4 * d4 + 3) * KP + kk] = a.w;
        float4 b = v4[idx];
        *(float4*)(Vs + kk * VP + 4 * d4) = b;
    }
    __syncthreads();

    for (int slot = w; slot < NQ; slot += 8) {
        int qi = qis[slot];
        int pidx = (bh * NQ + slot) * NSPLIT + split;
        if (qi < cs) {                    // chunk entirely masked for this query
            if (lane == 0) { g_pm[pidx] = NEGINF; g_pl[pidx] = 0.f; }
            continue;
        }
        int kend = min(CK, qi - cs + 1);
        const float* qrow = qs + slot * DD;
        bool do1 = (kend > 128);

        // QK: lane owns keys 4*lane..4*lane+3 (pass0) and +128 (pass1)
        float a0x = 0, a0y = 0, a0z = 0, a0w = 0;
        float a1x = 0, a1y = 0, a1z = 0, a1w = 0;
#pragma unroll
        for (int d = 0; d < DD; d++) {
            float qd = qrow[d];
            float4 kk0 = *(const float4*)(Kt + d * KP + 4 * lane);
            a0x += qd * kk0.x; a0y += qd * kk0.y; a0z += qd * kk0.z; a0w += qd * kk0.w;
        }
        if (do1) {
#pragma unroll
            for (int d = 0; d < DD; d++) {
                float qd = qrow[d];
                float4 kk1 = *(const float4*)(Kt + d * KP + 128 + 4 * lane);
                a1x += qd * kk1.x; a1y += qd * kk1.y; a1z += qd * kk1.z; a1w += qd * kk1.w;
            }
        }
        int kb = 4 * lane;
        float s0 = (kb + 0 < kend) ? a0x * 0.125f : NEGINF;
        float s1 = (kb + 1 < kend) ? a0y * 0.125f : NEGINF;
        float s2 = (kb + 2 < kend) ? a0z * 0.125f : NEGINF;
        float s3 = (kb + 3 < kend) ? a0w * 0.125f : NEGINF;
        int kb1 = 128 + kb;
        float s4 = (do1 && kb1 + 0 < kend) ? a1x * 0.125f : NEGINF;
        float s5 = (do1 && kb1 + 1 < kend) ? a1y * 0.125f : NEGINF;
        float s6 = (do1 && kb1 + 2 < kend) ? a1z * 0.125f : NEGINF;
        float s7 = (do1 && kb1 + 3 < kend) ? a1w * 0.125f : NEGINF;

        float m = fmaxf(fmaxf(fmaxf(s0, s1), fmaxf(s2, s3)),
                        fmaxf(fmaxf(s4, s5), fmaxf(s6, s7)));
#pragma unroll
        for (int o = 16; o > 0; o >>= 1)
            m = fmaxf(m, __shfl_xor_sync(0xffffffffu, m, o));

        float p0 = (kb + 0 < kend) ? __expf(s0 - m) : 0.f;
        float p1 = (kb + 1 < kend) ? __expf(s1 - m) : 0.f;
        float p2 = (kb + 2 < kend) ? __expf(s2 - m) : 0.f;
        float p3 = (kb + 3 < kend) ? __expf(s3 - m) : 0.f;
        float p4 = (do1 && kb1 + 0 < kend) ? __expf(s4 - m) : 0.f;
        float p5 = (do1 && kb1 + 1 < kend) ? __expf(s5 - m) : 0.f;
        float p6 = (do1 && kb1 + 2 < kend) ? __expf(s6 - m) : 0.f;
        float p7 = (do1 && kb1 + 3 < kend) ? __expf(s7 - m) : 0.f;
        float l = p0 + p1 + p2 + p3 + p4 + p5 + p6 + p7;
#pragma unroll
        for (int o = 16; o > 0; o >>= 1)
            l += __shfl_xor_sync(0xffffffffu, l, o);

        *(float4*)(ps + w * CK + kb) = make_float4(p0, p1, p2, p3);
        if (do1) *(float4*)(ps + w * CK + kb1) = make_float4(p4, p5, p6, p7);
        __syncwarp();

        // PV: lane owns dims 2*lane, 2*lane+1; p broadcast from smem
        float accx = 0.f, accy = 0.f;
        const float* psw = ps + w * CK;
        int k2 = 0;
        for (; k2 + 4 <= kend; k2 += 4) {
#pragma unroll
            for (int u = 0; u < 4; u++) {
                float pk = psw[k2 + u];
                float2 vv = *(const float2*)(Vs + (k2 + u) * VP + 2 * lane);
                accx += pk * vv.x; accy += pk * vv.y;
            }
        }
        for (; k2 < kend; k2++) {
            float pk = psw[k2];
            float2 vv = *(const float2*)(Vs + k2 * VP + 2 * lane);
            accx += pk * vv.x; accy += pk * vv.y;
        }

        float* pa = g_pacc + (long)pidx * DD;
        *(float2*)(pa + 2 * lane) = make_float2(accx, accy);
        if (lane == 0) { g_pm[pidx] = m; g_pl[pidx] = l; }
        __syncwarp();   // protect ps before next slot reuses it
    }
}

// ---------------- Stage D: chunked cumsum of value along L ----------------
__global__ void k_csum_part(const float* __restrict__ val) {
    int c = blockIdx.x, bh = blockIdx.y, d = threadIdx.x;
    const float* p = val + ((long)bh * LL + c * 64) * DD + d;
    float s = 0.f;
#pragma unroll 8
    for (int r = 0; r < 64; r++) s += p[r * DD];
    g_csum[(bh * 64 + c) * DD + d] = s;
}

__global__ void k_csum_scan() {
    int bh = blockIdx.x, d = threadIdx.x;
    float run = 0.f;
    for (int c = 0; c < 64; c++) {
        int i = (bh * 64 + c) * DD + d;
        float t = g_csum[i];
        g_coff[i] = run;
        run += t;
    }
}

__global__ void k_csum_apply(const float* __restrict__ val, float* __restrict__ out) {
    int c = blockIdx.x, bh = blockIdx.y, d = threadIdx.x;
    long base = ((long)bh * LL + c * 64) * DD + d;
    float run = g_coff[(bh * 64 + c) * DD + d];
#pragma unroll 8
    for (int r = 0; r < 64; r++) {
        run += val[base + r * DD];
        out[base + r * DD] = run;
    }
}

// ---------------- Stage E: combine split-K partials, scatter into output ----------------
__global__ void k_combine(float* __restrict__ out) {
    int slot = blockIdx.x, bh = blockIdx.y, d = threadIdx.x;
    int base = (bh * NQ + slot) * NSPLIT;
    float M = NEGINF;
#pragma unroll
    for (int s = 0; s < NSPLIT; s++) M = fmaxf(M, g_pm[base + s]);
    float Lsum = 0.f, acc = 0.f;
#pragma unroll
    for (int s = 0; s < NSPLIT; s++) {
        float l = g_pl[base + s];
        if (l > 0.f) {
            float sc = __expf(g_pm[base + s] - M);
            Lsum += l * sc;
            acc += sc * g_pacc[(long)(base + s) * DD + d];
        }
    }
    int qi = g_qidx[bh * NQ + slot];
    out[((long)bh * LL + qi) * DD + d] = acc / Lsum;
}

// ---------------- launch ----------------
extern "C" void kernel_launch(void* const* d_in, const int* in_sizes, int n_in,
                              void* d_out, int out_size) {
    const float* q = (const float*)d_in[0];
    const float* k = (const float*)d_in[1];
    const float* v = (const float*)d_in[2];
    const int* kidx = (const int*)d_in[3];
    float* out = (float*)d_out;
    (void)in_sizes; (void)n_in; (void)out_size;

    int smem_attn = (DD * KP + CK * VP + NQ * DD + 8 * CK) * 4 + NQ * 4 + 16;
    cudaFuncSetAttribute(k_attn, cudaFuncAttributeMaxDynamicSharedMemorySize, smem_attn);

    k_sparsity<<<BH * (LL / 8), 256>>>(q, k, kidx);
    k_topk<<<BH, 256>>>();
    k_attn<<<dim3(NSPLIT, BH), 256, smem_attn>>>(q, k, v);
    k_csum_part<<<dim3(64, BH), 64>>>(v);
    k_csum_scan<<<BH, 64>>>();
    k_csum_apply<<<dim3(64, BH), 64>>>(v, out);
    k_combine<<<dim3(NQ, BH), 64>>>(out);
}

// round 2
// speedup vs baseline: 2.3907x; 2.3907x over previous
#include <cuda_runtime.h>
#include <math.h>

// ProbSparseAttention: B=2,H=8,L=4096,D=64, num_keys=num_queries=45
#define BB 2
#define HH 8
#define LL 4096
#define DD 64
#define BH (BB*HH)
#define NK 45
#define NQ 45
#define NSPLIT 16
#define CK 256            // keys per attention chunk
#define KP 260            // Kt (transposed K) row stride in floats (KP/4=65)
#define VP 68             // Vs row stride in floats
#define NEGINF (-1e30f)

// ---------------- scratch (device globals; no allocation allowed) ----------------
__device__ float g_sparsity[BH * LL];
__device__ int   g_qidx[BH * NQ];
__device__ float g_pm[BH * NQ * NSPLIT];
__device__ float g_pl[BH * NQ * NSPLIT];
__device__ float g_pacc[BH * NQ * NSPLIT * DD];
__device__ float g_csum[BH * 64 * DD];
__device__ float g_coff[BH * 64 * DD];

// ---------------- Stage A: sparsity = max(scores_45) - sum(scores_45)/L ----------------
// One warp per query. 4 keys per iteration; 8 lanes cooperatively read each
// key row (2x LDG.128 per lane, fully coalesced 256B rows). q held in regs.
__global__ void k_sparsity(const float* __restrict__ q,
                           const float* __restrict__ key,
                           const int* __restrict__ kidx) {
    __shared__ float qs[8][DD];
    int w = threadIdx.x >> 5, lane = threadIdx.x & 31;
    int bh = blockIdx.x >> 9;                   // 512 blocks per bh
    int qrow = ((blockIdx.x & 511) << 3) + w;
    int g = lane >> 3, sub = lane & 7;

    // stage q row via warp, then pull this lane's dims into registers
    float2 qv = ((const float2*)q)[((long)bh * LL + qrow) * 32 + lane];
    ((float2*)qs[w])[lane] = qv;
    __syncwarp();
    float4 q0 = ((const float4*)qs[w])[sub];       // dims 4*sub..+3
    float4 q1 = ((const float4*)qs[w])[sub + 8];   // dims 32+4*sub..+3

    const float4* k4 = (const float4*)key + ((long)bh * LL) * 16;
    const int* krow_idx = kidx + qrow * NK;

    float m = NEGINF, ssum = 0.f;
#pragma unroll
    for (int it = 0; it < 12; it++) {
        int j = it * 4 + g;
        int ki = (j < NK) ? krow_idx[j] : 0;
        const float4* kr = k4 + (long)ki * 16;
        float4 a = kr[sub];
        float4 b = kr[sub + 8];
        float s = q0.x * a.x + q0.y * a.y + q0.z * a.z + q0.w * a.w
                + q1.x * b.x + q1.y * b.y + q1.z * b.z + q1.w * b.w;
        s += __shfl_xor_sync(0xffffffffu, s, 4);
        s += __shfl_xor_sync(0xffffffffu, s, 2);
        s += __shfl_xor_sync(0xffffffffu, s, 1);
        if (sub == 0 && j < NK) { m = fmaxf(m, s); ssum += s; }
    }
    // combine the 4 group leaders (lanes 0,8,16,24); non-leaders carry (-inf,0)
    m = fmaxf(m, __shfl_xor_sync(0xffffffffu, m, 8));
    m = fmaxf(m, __shfl_xor_sync(0xffffffffu, m, 16));
    ssum += __shfl_xor_sync(0xffffffffu, ssum, 8);
    ssum += __shfl_xor_sync(0xffffffffu, ssum, 16);
    if (lane == 0)
        g_sparsity[bh * LL + qrow] = m - ssum * (1.0f / LL);
}

// ---------------- Stage B: top-45 per (b,h) via 4-pass radix select ----------------
// Output order is irrelevant (scatter with distinct indices); we sort qidx
// ascending for attention load balance. Tie-break at threshold: smallest index.
__global__ void k_topk() {
    __shared__ unsigned us[LL];
    __shared__ int hist[256];
    __shared__ unsigned sprefix;
    __shared__ int sb_need, nGT, nTie;
    __shared__ int tiebuf[256];
    __shared__ int idxbuf[NQ];
    int bh = blockIdx.x, tid = threadIdx.x;

    for (int i = tid; i < LL; i += 256) {
        unsigned b = __float_as_uint(g_sparsity[bh * LL + i]);
        us[i] = (b & 0x80000000u) ? ~b : (b | 0x80000000u);
    }
    if (tid == 0) { sb_need = NQ; nGT = 0; nTie = 0; sprefix = 0; }
    __syncthreads();

    for (int pass = 0; pass < 4; pass++) {
        int shift = 24 - 8 * pass;
        hist[tid] = 0;
        if (tid < 0) {} // block is 256 == bins
        __syncthreads();
        unsigned pfx = sprefix;
        for (int i = tid; i < LL; i += 256) {
            unsigned u = us[i];
            if (pass == 0 || (u >> (shift + 8)) == pfx)
                atomicAdd(&hist[(u >> shift) & 255], 1);
        }
        __syncthreads();
        if (tid == 0) {
            int need = sb_need, c = 0, b;
            for (b = 255; b >= 0; b--) {
                if (c + hist[b] >= need) break;
                c += hist[b];
            }
            sprefix = (pfx << 8) | (unsigned)b;
            sb_need = need - c;
        }
        __syncthreads();
    }
    unsigned T = sprefix;
    int tieTake = sb_need;

    for (int i = tid; i < LL; i += 256) {
        unsigned u = us[i];
        if (u > T) { int p = atomicAdd(&nGT, 1); idxbuf[p] = i; }
        else if (u == T) { int p = atomicAdd(&nTie, 1); if (p < 256) tiebuf[p] = i; }
    }
    __syncthreads();
    if (tid == 0) {
        int nt = nTie < 256 ? nTie : 256;
        int base = nGT;
        for (int t = 0; t < tieTake; t++) {
            int bi = 0, bv = 0x7fffffff;
            for (int j = 0; j < nt; j++)
                if (tiebuf[j] < bv) { bv = tiebuf[j]; bi = j; }
            idxbuf[base + t] = bv;
            tiebuf[bi] = 0x7fffffff;
        }
        // sort ascending by query index (order-free for correctness)
        for (int a2 = 1; a2 < NQ; a2++) {
            int v = idxbuf[a2], b2 = a2 - 1;
            while (b2 >= 0 && idxbuf[b2] > v) { idxbuf[b2 + 1] = idxbuf[b2]; b2--; }
            idxbuf[b2 + 1] = v;
        }
        for (int a2 = 0; a2 < NQ; a2++) g_qidx[bh * NQ + a2] = idxbuf[a2];
    }
}

// ---------------- Stage C: split-K attention; 2 query slots per warp ----------------
__global__ void __launch_bounds__(256, 1)
k_attn(const float* __restrict__ q,
       const float* __restrict__ key,
       const float* __restrict__ val) {
    extern __shared__ float sm[];
    float* Kt = sm;                       // DD*KP
    float* Vs = Kt + DD * KP;             // CK*VP
    float* qs = Vs + CK * VP;             // NQ*DD
    float* ps = qs + NQ * DD;             // 8 warps * 2 * CK
    int* qis = (int*)(ps + 8 * 2 * CK);   // NQ

    int split = blockIdx.x, bh = blockIdx.y;
    int tid = threadIdx.x, w = tid >> 5, lane = tid & 31;
    int cs = split * CK;

    if (tid < NQ) qis[tid] = g_qidx[bh * NQ + tid];
    __syncthreads();

    for (int i = tid; i < NQ * DD / 4; i += 256) {
        int slot = i >> 4, d4 = i & 15;
        ((float4*)qs)[i] = ((const float4*)q)[((long)bh * LL + qis[slot]) * 16 + d4];
    }
    const float4* k4 = (const float4*)key + ((long)bh * LL + cs) * 16;
    const float4* v4 = (const float4*)val + ((long)bh * LL + cs) * 16;
#pragma unroll
    for (int it = 0; it < 16; it++) {
        int idx = tid + it * 256;
        int kk = idx >> 4, d4 = idx & 15;
        float4 a = k4[idx];
        Kt[(4 * d4 + 0) * KP + kk] = a.x;
        Kt[(4 * d4 + 1) * KP + kk] = a.y;
        Kt[(4 * d4 + 2) * KP + kk] = a.z;
        Kt[(4 * d4 + 3) * KP + kk] = a.w;
        *(float4*)(Vs + kk * VP + 4 * d4) = v4[idx];
    }
    __syncthreads();

    const float4* KtA = (const float4*)Kt;   // [d*65 + lane]

    for (int p = w; p < 24; p += 8) {
        int s0 = 2 * p, s1 = 2 * p + 1;
        bool a0 = s0 < NQ, a1 = s1 < NQ;
        int qi0 = a0 ? qis[s0] : 0;
        int qi1 = a1 ? qis[s1] : 0;
        int pidx0 = (bh * NQ + s0) * NSPLIT + split;
        int pidx1 = (bh * NQ + s1) * NSPLIT + split;
        int kend0 = a0 ? min(CK, qi0 - cs + 1) : 0; if (kend0 < 0) kend0 = 0;
        int kend1 = a1 ? min(CK, qi1 - cs + 1) : 0; if (kend1 < 0) kend1 = 0;
        if (a0 && kend0 == 0 && lane == 0) { g_pm[pidx0] = NEGINF; g_pl[pidx0] = 0.f; }
        if (a1 && kend1 == 0 && lane == 0) { g_pm[pidx1] = NEGINF; g_pl[pidx1] = 0.f; }
        int kendM = max(kend0, kend1);
        if (kendM == 0) continue;
        bool do1 = (kendM > 128);

        const float4* q0p = (const float4*)(qs + s0 * DD);
        const float4* q1p = (const float4*)(qs + s1 * DD);

        float A0[4] = {0, 0, 0, 0}, B0[4] = {0, 0, 0, 0};
        float A1[4] = {0, 0, 0, 0}, B1[4] = {0, 0, 0, 0};
#pragma unroll
        for (int d4 = 0; d4 < 16; d4++) {
            float4 q0v = q0p[d4], q1v = q1p[d4];
#pragma unroll
            for (int dd = 0; dd < 4; dd++) {
                float4 kk = KtA[(4 * d4 + dd) * 65 + lane];
                float qa = (&q0v.x)[dd], qb = (&q1v.x)[dd];
                A0[0] += qa * kk.x; A0[1] += qa * kk.y; A0[2] += qa * kk.z; A0[3] += qa * kk.w;
                B0[0] += qb * kk.x; B0[1] += qb * kk.y; B0[2] += qb * kk.z; B0[3] += qb * kk.w;
            }
        }
        if (do1) {
#pragma unroll
            for (int d4 = 0; d4 < 16; d4++) {
                float4 q0v = q0p[d4], q1v = q1p[d4];
#pragma unroll
                for (int dd = 0; dd < 4; dd++) {
                    float4 kk = KtA[(4 * d4 + dd) * 65 + 32 + lane];
                    float qa = (&q0v.x)[dd], qb = (&q1v.x)[dd];
                    A1[0] += qa * kk.x; A1[1] += qa * kk.y; A1[2] += qa * kk.z; A1[3] += qa * kk.w;
                    B1[0] += qb * kk.x; B1[1] += qb * kk.y; B1[2] += qb * kk.z; B1[3] += qb * kk.w;
                }
            }
        }

        float* psw0 = ps + w * 2 * CK;
        float* psw1 = psw0 + CK;
        int kb = 4 * lane, kb1 = 128 + 4 * lane;

        // ---- softmax slot0 ----
        float m0 = NEGINF, l0 = 0.f;
        {
            float sc[8];
#pragma unroll
            for (int u = 0; u < 4; u++) sc[u] = (kb + u < kend0) ? A0[u] * 0.125f : NEGINF;
#pragma unroll
            for (int u = 0; u < 4; u++) sc[4 + u] = (do1 && kb1 + u < kend0) ? A1[u] * 0.125f : NEGINF;
            float m = sc[0];
#pragma unroll
            for (int u = 1; u < 8; u++) m = fmaxf(m, sc[u]);
#pragma unroll
            for (int o = 16; o > 0; o >>= 1) m = fmaxf(m, __shfl_xor_sync(0xffffffffu, m, o));
            float pv[8], l = 0.f;
#pragma unroll
            for (int u = 0; u < 8; u++) {
                bool ok = (u < 4) ? (kb + u < kend0) : (do1 && kb1 + (u - 4) < kend0);
                pv[u] = ok ? __expf(sc[u] - m) : 0.f;
                l += pv[u];
            }
#pragma unroll
            for (int o = 16; o > 0; o >>= 1) l += __shfl_xor_sync(0xffffffffu, l, o);
            *(float4*)(psw0 + kb) = make_float4(pv[0], pv[1], pv[2], pv[3]);
            if (do1) *(float4*)(psw0 + kb1) = make_float4(pv[4], pv[5], pv[6], pv[7]);
            m0 = m; l0 = l;
        }
        // ---- softmax slot1 ----
        float m1 = NEGINF, l1 = 0.f;
        {
            float sc[8];
#pragma unroll
            for (int u = 0; u < 4; u++) sc[u] = (kb + u < kend1) ? B0[u] * 0.125f : NEGINF;
#pragma unroll
            for (int u = 0; u < 4; u++) sc[4 + u] = (do1 && kb1 + u < kend1) ? B1[u] * 0.125f : NEGINF;
            float m = sc[0];
#pragma unroll
            for (int u = 1; u < 8; u++) m = fmaxf(m, sc[u]);
#pragma unroll
            for (int o = 16; o > 0; o >>= 1) m = fmaxf(m, __shfl_xor_sync(0xffffffffu, m, o));
            float pv[8], l = 0.f;
#pragma unroll
            for (int u = 0; u < 8; u++) {
                bool ok = (u < 4) ? (kb + u < kend1) : (do1 && kb1 + (u - 4) < kend1);
                pv[u] = ok ? __expf(sc[u] - m) : 0.f;
                l += pv[u];
            }
#pragma unroll
            for (int o = 16; o > 0; o >>= 1) l += __shfl_xor_sync(0xffffffffu, l, o);
            *(float4*)(psw1 + kb) = make_float4(pv[0], pv[1], pv[2], pv[3]);
            if (do1) *(float4*)(psw1 + kb1) = make_float4(pv[4], pv[5], pv[6], pv[7]);
            m1 = m; l1 = l;
        }
        __syncwarp();

        // ---- PV: even keys -> lanes 0-15, odd keys -> lanes 16-31; float4 dims ----
        float4 acc0 = make_float4(0, 0, 0, 0), acc1 = make_float4(0, 0, 0, 0);
        int half = lane >> 4, dl = lane & 15;
        for (int k = half; k < kendM; k += 2) {
            float4 vv = *(const float4*)(Vs + k * VP + 4 * dl);
            float p0 = psw0[k], p1 = psw1[k];
            acc0.x += p0 * vv.x; acc0.y += p0 * vv.y; acc0.z += p0 * vv.z; acc0.w += p0 * vv.w;
            acc1.x += p1 * vv.x; acc1.y += p1 * vv.y; acc1.z += p1 * vv.z; acc1.w += p1 * vv.w;
        }
        acc0.x += __shfl_down_sync(0xffffffffu, acc0.x, 16);
        acc0.y += __shfl_down_sync(0xffffffffu, acc0.y, 16);
        acc0.z += __shfl_down_sync(0xffffffffu, acc0.z, 16);
        acc0.w += __shfl_down_sync(0xffffffffu, acc0.w, 16);
        acc1.x += __shfl_down_sync(0xffffffffu, acc1.x, 16);
        acc1.y += __shfl_down_sync(0xffffffffu, acc1.y, 16);
        acc1.z += __shfl_down_sync(0xffffffffu, acc1.z, 16);
        acc1.w += __shfl_down_sync(0xffffffffu, acc1.w, 16);

        if (lane < 16) {
            if (kend0 > 0) ((float4*)(g_pacc + (long)pidx0 * DD))[dl] = acc0;
            if (kend1 > 0) ((float4*)(g_pacc + (long)pidx1 * DD))[dl] = acc1;
        }
        if (lane == 0) {
            if (kend0 > 0) { g_pm[pidx0] = m0; g_pl[pidx0] = l0; }
            if (kend1 > 0) { g_pm[pidx1] = m1; g_pl[pidx1] = l1; }
        }
        __syncwarp();
    }
}

// ---------------- Stage D: chunked cumsum of value along L ----------------
__global__ void k_csum_part(const float* __restrict__ val) {
    int c = blockIdx.x * 4 + (threadIdx.x >> 6), bh = blockIdx.y, d = threadIdx.x & 63;
    const float* p = val + ((long)bh * LL + c * 64) * DD + d;
    float s = 0.f;
#pragma unroll 16
    for (int r = 0; r < 64; r++) s += p[r * DD];
    g_csum[(bh * 64 + c) * DD + d] = s;
}

__global__ void k_csum_scan() {
    int bh = blockIdx.x, d = threadIdx.x;
    float run = 0.f;
#pragma unroll 8
    for (int c = 0; c < 64; c++) {
        int i = (bh * 64 + c) * DD + d;
        float t = g_csum[i];
        g_coff[i] = run;
        run += t;
    }
}

__global__ void k_csum_apply(const float* __restrict__ val, float* __restrict__ out) {
    int c = blockIdx.x * 4 + (threadIdx.x >> 6), bh = blockIdx.y, d = threadIdx.x & 63;
    long base = ((long)bh * LL + c * 64) * DD + d;
    float run = g_coff[(bh * 64 + c) * DD + d];
#pragma unroll 16
    for (int r = 0; r < 64; r++) {
        run += val[base + r * DD];
        out[base + r * DD] = run;
    }
}

// ---------------- Stage E: combine split-K partials, scatter into output ----------------
__global__ void k_combine(float* __restrict__ out) {
    int slot = blockIdx.x, bh = blockIdx.y, d = threadIdx.x;
    int base = (bh * NQ + slot) * NSPLIT;
    float M = NEGINF;
#pragma unroll
    for (int s = 0; s < NSPLIT; s++) M = fmaxf(M, g_pm[base + s]);
    float Lsum = 0.f, acc = 0.f;
#pragma unroll
    for (int s = 0; s < NSPLIT; s++) {
        float l = g_pl[base + s];
        if (l > 0.f) {
            float sc = __expf(g_pm[base + s] - M);
            Lsum += l * sc;
            acc += sc * g_pacc[(long)(base + s) * DD + d];
        }
    }
    int qi = g_qidx[bh * NQ + slot];
    out[((long)bh * LL + qi) * DD + d] = acc / Lsum;
}

// ---------------- launch ----------------
extern "C" void kernel_launch(void* const* d_in, const int* in_sizes, int n_in,
                              void* d_out, int out_size) {
    const float* q = (const float*)d_in[0];
    const float* k = (const float*)d_in[1];
    const float* v = (const float*)d_in[2];
    const int* kidx = (const int*)d_in[3];
    float* out = (float*)d_out;
    (void)in_sizes; (void)n_in; (void)out_size;

    int smem_attn = (DD * KP + CK * VP + NQ * DD + 8 * 2 * CK) * 4 + NQ * 4 + 16;
    cudaFuncSetAttribute(k_attn, cudaFuncAttributeMaxDynamicSharedMemorySize, smem_attn);

    k_sparsity<<<BH * (LL / 8), 256>>>(q, k, kidx);
    k_topk<<<BH, 256>>>();
    k_attn<<<dim3(NSPLIT, BH), 256, smem_attn>>>(q, k, v);
    k_csum_part<<<dim3(16, BH), 256>>>(v);
    k_csum_scan<<<BH, 64>>>();
    k_csum_apply<<<dim3(16, BH), 256>>>(v, out);
    k_combine<<<dim3(NQ, BH), 64>>>(out);
}